// round 1
// baseline (speedup 1.0000x reference)
#include <cuda_runtime.h>
#include <cuda_bf16.h>
#include <float.h>

// Problem shape (fixed per reference)
#define BATCH 32
#define SEQ   4096
#define HID   1024
#define TOP   512
#define CATK  (2*HID + TOP)   // 2560

#define NSPLIT 16             // S-splits per batch in attention pass
#define ROWS_PER_SPLIT (SEQ / NSPLIT)   // 256
#define RPC 4                 // rows folded per chunk (MLP)

// ---------------- scratch (__device__ globals; no allocations) --------------
__device__ float g_gamma [BATCH * HID];
__device__ float g_scores[BATCH * SEQ];
__device__ float g_cpart [BATCH * NSPLIT * HID];
__device__ float g_mzpart[BATCH * NSPLIT * 2];
__device__ float g_cat   [BATCH * CATK];
__device__ float g_mz    [BATCH * 2];      // {m_global, 1/Z}

// ---------------------------------------------------------------------------
// Kernel 1/5: small GEMM  out[b][h] = act( bias[h] + sum_k in[b][k]*W[h][k] )
// grid.x = Hout/8, block = 256 (8 warps, one output row h per warp, all 32 b)
// K must be a multiple of 256.
// ---------------------------------------------------------------------------
__global__ void __launch_bounds__(256)
small_gemm_kernel(const float* __restrict__ in, const float* __restrict__ W,
                  const float* __restrict__ bias, float* __restrict__ out,
                  int K, int Hout, int act)
{
    __shared__ float4 tile[BATCH * 64];   // 32 b x 256 k  (32 KB)
    const int t    = threadIdx.x;
    const int warp = t >> 5;
    const int lane = t & 31;
    const int h    = blockIdx.x * 8 + warp;

    float acc[BATCH];
    #pragma unroll
    for (int b = 0; b < BATCH; ++b) acc[b] = 0.f;

    for (int k0 = 0; k0 < K; k0 += 256) {
        // cooperative tile load: 2048 float4
        #pragma unroll
        for (int i = 0; i < 8; ++i) {
            int idx = t + i * 256;
            int bb  = idx >> 6;           // / 64 float4 per row
            int kk  = idx & 63;
            tile[idx] = ((const float4*)(in + (size_t)bb * K + k0))[kk];
        }
        __syncthreads();

        #pragma unroll
        for (int c = 0; c < 2; ++c) {
            float4 w4 = ((const float4*)(W + (size_t)h * K + k0 + c * 128))[lane];
            #pragma unroll
            for (int bb = 0; bb < BATCH; ++bb) {
                float4 xv = tile[bb * 64 + c * 32 + lane];
                acc[bb] += w4.x * xv.x + w4.y * xv.y + w4.z * xv.z + w4.w * xv.w;
            }
        }
        __syncthreads();
    }

    // butterfly-reduce all 32 accumulators across the warp
    #pragma unroll
    for (int off = 16; off; off >>= 1)
        #pragma unroll
        for (int bb = 0; bb < BATCH; ++bb)
            acc[bb] += __shfl_xor_sync(0xFFFFFFFFu, acc[bb], off);

    float v = acc[lane] + bias[h];        // lane <-> batch
    if (act) v = tanhf(v);
    out[(size_t)lane * Hout + h] = v;
}

// ---------------------------------------------------------------------------
// Kernel 2/5: fused scores + online softmax + partial weighted sum.
// grid = (NSPLIT, BATCH), block = 256. Single pass over context.
// ---------------------------------------------------------------------------
__global__ void __launch_bounds__(256)
attn_pass_kernel(const float* __restrict__ ctx)
{
    __shared__ float red[8][RPC];
    __shared__ float sc[RPC];

    const int t     = threadIdx.x;
    const int warp  = t >> 5;
    const int lane  = t & 31;
    const int split = blockIdx.x;
    const int b     = blockIdx.y;

    const float4 gr = ((const float4*)(g_gamma + b * HID))[t];

    const float* base = ctx + ((size_t)b * SEQ + (size_t)split * ROWS_PER_SPLIT) * HID;

    float  m = -FLT_MAX, Z = 0.f;
    float4 cacc = make_float4(0.f, 0.f, 0.f, 0.f);

    for (int c = 0; c < ROWS_PER_SPLIT / RPC; ++c) {
        float4 v[RPC];
        #pragma unroll
        for (int j = 0; j < RPC; ++j)
            v[j] = ((const float4*)(base + (size_t)(c * RPC + j) * HID))[t];

        float p[RPC];
        #pragma unroll
        for (int j = 0; j < RPC; ++j)
            p[j] = v[j].x * gr.x + v[j].y * gr.y + v[j].z * gr.z + v[j].w * gr.w;

        #pragma unroll
        for (int off = 16; off; off >>= 1)
            #pragma unroll
            for (int j = 0; j < RPC; ++j)
                p[j] += __shfl_xor_sync(0xFFFFFFFFu, p[j], off);

        if (lane == 0) {
            #pragma unroll
            for (int j = 0; j < RPC; ++j) red[warp][j] = p[j];
        }
        __syncthreads();

        if (t < RPC) {
            float s = 0.f;
            #pragma unroll
            for (int w = 0; w < 8; ++w) s += red[w][t];
            sc[t] = s;
            g_scores[b * SEQ + split * ROWS_PER_SPLIT + c * RPC + t] = s;
        }
        __syncthreads();

        float s[RPC];
        #pragma unroll
        for (int j = 0; j < RPC; ++j) s[j] = sc[j];

        float mc = s[0];
        #pragma unroll
        for (int j = 1; j < RPC; ++j) mc = fmaxf(mc, s[j]);
        const float mnew  = fmaxf(m, mc);
        const float scale = __expf(m - mnew);   // m=-FLT_MAX -> 0, safe

        float e[RPC];
        float esum = 0.f;
        #pragma unroll
        for (int j = 0; j < RPC; ++j) { e[j] = __expf(s[j] - mnew); esum += e[j]; }

        Z = Z * scale + esum;
        cacc.x = cacc.x * scale; cacc.y = cacc.y * scale;
        cacc.z = cacc.z * scale; cacc.w = cacc.w * scale;
        #pragma unroll
        for (int j = 0; j < RPC; ++j) {
            cacc.x += e[j] * v[j].x;  cacc.y += e[j] * v[j].y;
            cacc.z += e[j] * v[j].z;  cacc.w += e[j] * v[j].w;
        }
        m = mnew;
        // NOTE: no extra barrier needed; next chunk's red-write happens after
        // the __syncthreads() above, and sc is re-written only after the next
        // first barrier.
    }

    ((float4*)(g_cpart + ((size_t)b * NSPLIT + split) * HID))[t] = cacc;
    if (t == 0) {
        g_mzpart[(b * NSPLIT + split) * 2 + 0] = m;
        g_mzpart[(b * NSPLIT + split) * 2 + 1] = Z;
    }
}

// ---------------------------------------------------------------------------
// Kernel 3/5: cross-split reduction -> c_t, (m,1/Z); also builds cat buffer.
// grid = BATCH, block = 256.
// ---------------------------------------------------------------------------
__global__ void __launch_bounds__(256)
reduce_c_kernel(const float* __restrict__ x, const float* __restrict__ topic)
{
    const int b = blockIdx.x;
    const int t = threadIdx.x;

    float mg = -FLT_MAX;
    #pragma unroll
    for (int i = 0; i < NSPLIT; ++i)
        mg = fmaxf(mg, g_mzpart[(b * NSPLIT + i) * 2 + 0]);

    float Zg = 0.f;
    float wsc[NSPLIT];
    #pragma unroll
    for (int i = 0; i < NSPLIT; ++i) {
        float mi = g_mzpart[(b * NSPLIT + i) * 2 + 0];
        float zi = g_mzpart[(b * NSPLIT + i) * 2 + 1];
        wsc[i] = __expf(mi - mg);
        Zg += zi * wsc[i];
    }
    const float inv = 1.f / Zg;

    float4 c = make_float4(0.f, 0.f, 0.f, 0.f);
    #pragma unroll
    for (int i = 0; i < NSPLIT; ++i) {
        float4 cp = ((const float4*)(g_cpart + ((size_t)b * NSPLIT + i) * HID))[t];
        c.x += wsc[i] * cp.x;  c.y += wsc[i] * cp.y;
        c.z += wsc[i] * cp.z;  c.w += wsc[i] * cp.w;
    }
    c.x *= inv; c.y *= inv; c.z *= inv; c.w *= inv;

    ((float4*)(g_cat + (size_t)b * CATK))[t] = c;
    ((float4*)(g_cat + (size_t)b * CATK + HID))[t] =
        ((const float4*)(x + (size_t)b * HID))[t];
    if (t < TOP / 4)
        ((float4*)(g_cat + (size_t)b * CATK + 2 * HID))[t] =
            ((const float4*)(topic + (size_t)b * TOP))[t];

    if (t == 0) { g_mz[b * 2 + 0] = mg; g_mz[b * 2 + 1] = inv; }
}

// ---------------------------------------------------------------------------
// Kernel 4/5: weights[b][s] = exp(score - m) * invZ   (written to d_out tail)
// ---------------------------------------------------------------------------
__global__ void __launch_bounds__(256)
weights_kernel(float* __restrict__ out_w)
{
    const int i = blockIdx.x * 256 + threadIdx.x;     // 0 .. BATCH*SEQ-1
    const int b = i >> 12;                            // / SEQ
    out_w[i] = __expf(g_scores[i] - g_mz[b * 2 + 0]) * g_mz[b * 2 + 1];
}

// ---------------------------------------------------------------------------
extern "C" void kernel_launch(void* const* d_in, const int* in_sizes, int n_in,
                              void* d_out, int out_size)
{
    const float* x     = (const float*)d_in[0];
    const float* ctx   = (const float*)d_in[1];
    const float* topic = (const float*)d_in[2];
    const float* W_in  = (const float*)d_in[3];
    const float* b_in  = (const float*)d_in[4];
    const float* W_out = (const float*)d_in[5];
    const float* b_out = (const float*)d_in[6];

    float* out  = (float*)d_out;                 // [BATCH,HID] output
    float* outw = out + BATCH * HID;             // [BATCH,SEQ] weights

    float* gamma_ptr;
    cudaGetSymbolAddress((void**)&gamma_ptr, g_gamma);
    float* cat_ptr;
    cudaGetSymbolAddress((void**)&cat_ptr, g_cat);

    // 1) gamma = x @ W_in^T + b_in
    small_gemm_kernel<<<HID / 8, 256>>>(x, W_in, b_in, gamma_ptr, HID, HID, 0);

    // 2) fused scores + online softmax + partial c_t (single context pass)
    attn_pass_kernel<<<dim3(NSPLIT, BATCH), 256>>>(ctx);

    // 3) cross-split reduce + build cat = [c_t | x | topic]
    reduce_c_kernel<<<BATCH, 256>>>(x, topic);

    // 4) softmax weights -> output tail
    weights_kernel<<<(BATCH * SEQ) / 256, 256>>>(outw);

    // 5) output = tanh(cat @ W_out^T + b_out)
    small_gemm_kernel<<<HID / 8, 256>>>(cat_ptr, W_out, b_out, out, CATK, HID, 1);
}

// round 2
// speedup vs baseline: 1.0850x; 1.0850x over previous
#include <cuda_runtime.h>
#include <cuda_bf16.h>
#include <float.h>

// Problem shape (fixed per reference)
#define BATCH 32
#define SEQ   4096
#define HID   1024
#define TOP   512
#define CATK  (2*HID + TOP)   // 2560

#define NSPLIT 16                        // S-splits per batch in attention pass
#define ROWS_PER_SPLIT (SEQ / NSPLIT)    // 256 rows per CTA
#define WARPS 8
#define ROWS_PER_WARP (ROWS_PER_SPLIT / WARPS)  // 32 rows per warp
#define VPL 8                            // float4 per lane per row (1024/4/32)

// ---------------- scratch (__device__ globals; no allocations) --------------
__device__ float g_gamma [BATCH * HID];
__device__ float g_scores[BATCH * SEQ];
__device__ float g_cpart [BATCH * NSPLIT * HID];
__device__ float g_mzpart[BATCH * NSPLIT * 2];
__device__ float g_cat   [BATCH * CATK];
__device__ float g_mz    [BATCH * 2];      // {m_global, 1/Z}

// ---------------------------------------------------------------------------
// Kernel 1/5: small GEMM  out[b][h] = act( bias[h] + sum_k in[b][k]*W[h][k] )
// grid.x = Hout/8, block = 256 (8 warps, one output row h per warp, all 32 b)
// K must be a multiple of 256.
// ---------------------------------------------------------------------------
__global__ void __launch_bounds__(256)
small_gemm_kernel(const float* __restrict__ in, const float* __restrict__ W,
                  const float* __restrict__ bias, float* __restrict__ out,
                  int K, int Hout, int act)
{
    __shared__ float4 tile[BATCH * 64];   // 32 b x 256 k  (32 KB)
    const int t    = threadIdx.x;
    const int warp = t >> 5;
    const int lane = t & 31;
    const int h    = blockIdx.x * 8 + warp;

    float acc[BATCH];
    #pragma unroll
    for (int b = 0; b < BATCH; ++b) acc[b] = 0.f;

    for (int k0 = 0; k0 < K; k0 += 256) {
        #pragma unroll
        for (int i = 0; i < 8; ++i) {
            int idx = t + i * 256;
            int bb  = idx >> 6;
            int kk  = idx & 63;
            tile[idx] = ((const float4*)(in + (size_t)bb * K + k0))[kk];
        }
        __syncthreads();

        #pragma unroll
        for (int c = 0; c < 2; ++c) {
            float4 w4 = ((const float4*)(W + (size_t)h * K + k0 + c * 128))[lane];
            #pragma unroll
            for (int bb = 0; bb < BATCH; ++bb) {
                float4 xv = tile[bb * 64 + c * 32 + lane];
                acc[bb] += w4.x * xv.x + w4.y * xv.y + w4.z * xv.z + w4.w * xv.w;
            }
        }
        __syncthreads();
    }

    #pragma unroll
    for (int off = 16; off; off >>= 1)
        #pragma unroll
        for (int bb = 0; bb < BATCH; ++bb)
            acc[bb] += __shfl_xor_sync(0xFFFFFFFFu, acc[bb], off);

    float v = acc[lane] + bias[h];        // lane <-> batch
    if (act) v = tanhf(v);
    out[(size_t)lane * Hout + h] = v;
}

// ---------------------------------------------------------------------------
// Kernel 2/5: warp-autonomous fused scores + online softmax + weighted sum.
// Each warp owns whole rows; NO barriers in the mainloop. One smem combine
// at the end per CTA. grid = (NSPLIT, BATCH), block = 256.
// ---------------------------------------------------------------------------
__global__ void __launch_bounds__(256, 2)
attn_pass_kernel(const float* __restrict__ ctx)
{
    __shared__ float s_c[WARPS][HID];     // 32 KB
    __shared__ float s_m[WARPS], s_Z[WARPS];

    const int t     = threadIdx.x;
    const int warp  = t >> 5;
    const int lane  = t & 31;
    const int split = blockIdx.x;
    const int b     = blockIdx.y;

    // gamma, accumulator: lane l holds float4 indices l + 32*i
    float4 g[VPL];
    {
        const float4* gp = (const float4*)(g_gamma + (size_t)b * HID);
        #pragma unroll
        for (int i = 0; i < VPL; ++i) g[i] = gp[lane + 32 * i];
    }

    const int row0 = split * ROWS_PER_SPLIT + warp * ROWS_PER_WARP;
    const float* base = ctx + ((size_t)b * SEQ + row0) * HID;

    float  m = -FLT_MAX, Z = 0.f;
    float4 c[VPL];
    #pragma unroll
    for (int i = 0; i < VPL; ++i) c[i] = make_float4(0.f, 0.f, 0.f, 0.f);

    for (int r = 0; r < ROWS_PER_WARP; ++r) {
        const float4* vp = (const float4*)(base + (size_t)r * HID);
        float4 v[VPL];
        #pragma unroll
        for (int i = 0; i < VPL; ++i) v[i] = vp[lane + 32 * i];

        float p = 0.f;
        #pragma unroll
        for (int i = 0; i < VPL; ++i)
            p += v[i].x * g[i].x + v[i].y * g[i].y + v[i].z * g[i].z + v[i].w * g[i].w;

        #pragma unroll
        for (int off = 16; off; off >>= 1)
            p += __shfl_xor_sync(0xFFFFFFFFu, p, off);   // all lanes get sum

        if (lane == 0) g_scores[(size_t)b * SEQ + row0 + r] = p;

        if (p > m) {                         // warp-uniform branch, rare
            const float scale = __expf(m - p);
            Z *= scale;
            #pragma unroll
            for (int i = 0; i < VPL; ++i) {
                c[i].x *= scale; c[i].y *= scale;
                c[i].z *= scale; c[i].w *= scale;
            }
            m = p;
        }
        const float e = __expf(p - m);
        Z += e;
        #pragma unroll
        for (int i = 0; i < VPL; ++i) {
            c[i].x += e * v[i].x;  c[i].y += e * v[i].y;
            c[i].z += e * v[i].z;  c[i].w += e * v[i].w;
        }
    }

    // ---- per-CTA combine of the 8 warps ----
    #pragma unroll
    for (int i = 0; i < VPL; ++i)
        ((float4*)s_c[warp])[lane + 32 * i] = c[i];
    if (lane == 0) { s_m[warp] = m; s_Z[warp] = Z; }
    __syncthreads();

    float mg = s_m[0];
    #pragma unroll
    for (int w = 1; w < WARPS; ++w) mg = fmaxf(mg, s_m[w]);

    float wsc[WARPS], Zg = 0.f;
    #pragma unroll
    for (int w = 0; w < WARPS; ++w) {
        wsc[w] = __expf(s_m[w] - mg);
        Zg += s_Z[w] * wsc[w];
    }

    float4 acc = make_float4(0.f, 0.f, 0.f, 0.f);
    #pragma unroll
    for (int w = 0; w < WARPS; ++w) {
        float4 cw = ((const float4*)s_c[w])[t];
        acc.x += wsc[w] * cw.x;  acc.y += wsc[w] * cw.y;
        acc.z += wsc[w] * cw.z;  acc.w += wsc[w] * cw.w;
    }
    ((float4*)(g_cpart + ((size_t)b * NSPLIT + split) * HID))[t] = acc;
    if (t == 0) {
        g_mzpart[(b * NSPLIT + split) * 2 + 0] = mg;
        g_mzpart[(b * NSPLIT + split) * 2 + 1] = Zg;
    }
}

// ---------------------------------------------------------------------------
// Kernel 3/5: cross-split reduction -> c_t, (m,1/Z); also builds cat buffer.
// grid = BATCH, block = 256.
// ---------------------------------------------------------------------------
__global__ void __launch_bounds__(256)
reduce_c_kernel(const float* __restrict__ x, const float* __restrict__ topic)
{
    const int b = blockIdx.x;
    const int t = threadIdx.x;

    float mg = -FLT_MAX;
    #pragma unroll
    for (int i = 0; i < NSPLIT; ++i)
        mg = fmaxf(mg, g_mzpart[(b * NSPLIT + i) * 2 + 0]);

    float Zg = 0.f;
    float wsc[NSPLIT];
    #pragma unroll
    for (int i = 0; i < NSPLIT; ++i) {
        float mi = g_mzpart[(b * NSPLIT + i) * 2 + 0];
        float zi = g_mzpart[(b * NSPLIT + i) * 2 + 1];
        wsc[i] = __expf(mi - mg);
        Zg += zi * wsc[i];
    }
    const float inv = 1.f / Zg;

    float4 c = make_float4(0.f, 0.f, 0.f, 0.f);
    #pragma unroll
    for (int i = 0; i < NSPLIT; ++i) {
        float4 cp = ((const float4*)(g_cpart + ((size_t)b * NSPLIT + i) * HID))[t];
        c.x += wsc[i] * cp.x;  c.y += wsc[i] * cp.y;
        c.z += wsc[i] * cp.z;  c.w += wsc[i] * cp.w;
    }
    c.x *= inv; c.y *= inv; c.z *= inv; c.w *= inv;

    ((float4*)(g_cat + (size_t)b * CATK))[t] = c;
    ((float4*)(g_cat + (size_t)b * CATK + HID))[t] =
        ((const float4*)(x + (size_t)b * HID))[t];
    if (t < TOP / 4)
        ((float4*)(g_cat + (size_t)b * CATK + 2 * HID))[t] =
            ((const float4*)(topic + (size_t)b * TOP))[t];

    if (t == 0) { g_mz[b * 2 + 0] = mg; g_mz[b * 2 + 1] = inv; }
}

// ---------------------------------------------------------------------------
// Kernel 4/5: weights[b][s] = exp(score - m) * invZ, float4-vectorized.
// grid = 128, block = 256; one float4 per thread.
// ---------------------------------------------------------------------------
__global__ void __launch_bounds__(256)
weights_kernel(float* __restrict__ out_w)
{
    const int i = blockIdx.x * 256 + threadIdx.x;    // float4 index, 0..32767
    const int b = i >> 10;                           // (i*4)/SEQ
    const float m   = g_mz[b * 2 + 0];
    const float inv = g_mz[b * 2 + 1];
    float4 s = ((const float4*)g_scores)[i];
    float4 w;
    w.x = __expf(s.x - m) * inv;
    w.y = __expf(s.y - m) * inv;
    w.z = __expf(s.z - m) * inv;
    w.w = __expf(s.w - m) * inv;
    ((float4*)out_w)[i] = w;
}

// ---------------------------------------------------------------------------
extern "C" void kernel_launch(void* const* d_in, const int* in_sizes, int n_in,
                              void* d_out, int out_size)
{
    const float* x     = (const float*)d_in[0];
    const float* ctx   = (const float*)d_in[1];
    const float* topic = (const float*)d_in[2];
    const float* W_in  = (const float*)d_in[3];
    const float* b_in  = (const float*)d_in[4];
    const float* W_out = (const float*)d_in[5];
    const float* b_out = (const float*)d_in[6];

    float* out  = (float*)d_out;                 // [BATCH,HID] output
    float* outw = out + BATCH * HID;             // [BATCH,SEQ] weights

    float* gamma_ptr;
    cudaGetSymbolAddress((void**)&gamma_ptr, g_gamma);
    float* cat_ptr;
    cudaGetSymbolAddress((void**)&cat_ptr, g_cat);

    // 1) gamma = x @ W_in^T + b_in
    small_gemm_kernel<<<HID / 8, 256>>>(x, W_in, b_in, gamma_ptr, HID, HID, 0);

    // 2) fused scores + online softmax + partial c_t (single context pass)
    attn_pass_kernel<<<dim3(NSPLIT, BATCH), 256>>>(ctx);

    // 3) cross-split reduce + build cat = [c_t | x | topic]
    reduce_c_kernel<<<BATCH, 256>>>(x, topic);

    // 4) softmax weights -> output tail
    weights_kernel<<<(BATCH * SEQ) / 4 / 256, 256>>>(outw);

    // 5) output = tanh(cat @ W_out^T + b_out)
    small_gemm_kernel<<<HID / 8, 256>>>(cat_ptr, W_out, b_out, out, CATK, HID, 1);
}

// round 4
// speedup vs baseline: 1.1031x; 1.0167x over previous
#include <cuda_runtime.h>
#include <cuda_bf16.h>
#include <float.h>
#include <cstdint>

// Problem shape (fixed per reference)
#define BATCH 32
#define SEQ   4096
#define HID   1024
#define TOP   512
#define CATK  (2*HID + TOP)   // 2560

#define NSPLIT 16                        // S-splits per batch in attention pass
#define ROWS_PER_SPLIT (SEQ / NSPLIT)    // 256 rows per CTA
#define WARPS 8
#define ROWS_PER_WARP (ROWS_PER_SPLIT / WARPS)  // 32 rows per warp
#define VPL 8                            // float4 per lane per row (1024/4/32)
#define ATTN_SMEM (WARPS * 2 * 256 * 16) // 64 KB: per-warp double row buffer

// ---------------- scratch (__device__ globals; no allocations) --------------
__device__ float g_gamma [BATCH * HID];
__device__ float g_scores[BATCH * SEQ];
__device__ float g_cpart [BATCH * NSPLIT * HID];
__device__ float g_mzpart[BATCH * NSPLIT * 2];
__device__ float g_cat   [BATCH * CATK];

// ---------------------------------------------------------------------------
// Kernel 1/4: small GEMM  out[b][h] = act( bias[h] + sum_k in[b][k]*W[h][k] )
// grid.x = Hout/8, block = 256 (8 warps, one output row h per warp, all 32 b)
// ---------------------------------------------------------------------------
__global__ void __launch_bounds__(256)
small_gemm_kernel(const float* __restrict__ in, const float* __restrict__ W,
                  const float* __restrict__ bias, float* __restrict__ out,
                  int K, int Hout, int act)
{
    __shared__ float4 tile[BATCH * 64];   // 32 b x 256 k  (32 KB)
    const int t    = threadIdx.x;
    const int warp = t >> 5;
    const int lane = t & 31;
    const int h    = blockIdx.x * 8 + warp;

    float acc[BATCH];
    #pragma unroll
    for (int b = 0; b < BATCH; ++b) acc[b] = 0.f;

    for (int k0 = 0; k0 < K; k0 += 256) {
        #pragma unroll
        for (int i = 0; i < 8; ++i) {
            int idx = t + i * 256;
            int bb  = idx >> 6;
            int kk  = idx & 63;
            tile[idx] = ((const float4*)(in + (size_t)bb * K + k0))[kk];
        }
        __syncthreads();

        #pragma unroll
        for (int c = 0; c < 2; ++c) {
            float4 w4 = ((const float4*)(W + (size_t)h * K + k0 + c * 128))[lane];
            #pragma unroll
            for (int bb = 0; bb < BATCH; ++bb) {
                float4 xv = tile[bb * 64 + c * 32 + lane];
                acc[bb] += w4.x * xv.x + w4.y * xv.y + w4.z * xv.z + w4.w * xv.w;
            }
        }
        __syncthreads();
    }

    #pragma unroll
    for (int off = 16; off; off >>= 1)
        #pragma unroll
        for (int bb = 0; bb < BATCH; ++bb)
            acc[bb] += __shfl_xor_sync(0xFFFFFFFFu, acc[bb], off);

    float v = acc[lane] + bias[h];        // lane <-> batch
    if (act) v = tanhf(v);
    out[(size_t)lane * Hout + h] = v;
}

// ---------------------------------------------------------------------------
// Kernel 2/4: warp-autonomous fused scores + online softmax + weighted sum,
// with cp.async double-buffered row staging (deep MLP, no register cost).
// grid = (NSPLIT, BATCH), block = 256, dynamic smem 64KB.
// ---------------------------------------------------------------------------
__device__ __forceinline__ void stage_row(uint32_t dst_base, const float4* src)
{
    #pragma unroll
    for (int i = 0; i < VPL; ++i)
        asm volatile("cp.async.cg.shared.global [%0], [%1], 16;\n"
                     :: "r"(dst_base + i * 512), "l"(src + i * 32));
}

__global__ void __launch_bounds__(256, 2)
attn_pass_kernel(const float* __restrict__ ctx)
{
    extern __shared__ float4 sbuf[];          // [WARPS][2][256] float4
    __shared__ float s_m[WARPS], s_Z[WARPS];

    const int t     = threadIdx.x;
    const int warp  = t >> 5;
    const int lane  = t & 31;
    const int split = blockIdx.x;
    const int b     = blockIdx.y;

    // gamma: lane l holds float4 indices l + 32*i
    float4 g[VPL];
    {
        const float4* gp = (const float4*)(g_gamma + (size_t)b * HID);
        #pragma unroll
        for (int i = 0; i < VPL; ++i) g[i] = gp[lane + 32 * i];
    }

    const int row0 = split * ROWS_PER_SPLIT + warp * ROWS_PER_WARP;
    const float4* base = (const float4*)(ctx + ((size_t)b * SEQ + row0) * HID);

    float4* wbuf = sbuf + warp * 2 * 256;
    const uint32_t wbuf_addr =
        (uint32_t)__cvta_generic_to_shared(wbuf) + (uint32_t)lane * 16;

    // prologue: stage rows 0,1
    #pragma unroll
    for (int pre = 0; pre < 2; ++pre) {
        stage_row(wbuf_addr + pre * 4096, base + pre * 256 + lane);
        asm volatile("cp.async.commit_group;\n");
    }

    float  m = -FLT_MAX, Z = 0.f;
    float4 c[VPL];
    #pragma unroll
    for (int i = 0; i < VPL; ++i) c[i] = make_float4(0.f, 0.f, 0.f, 0.f);

    for (int r = 0; r < ROWS_PER_WARP; ++r) {
        asm volatile("cp.async.wait_group 1;\n");
        __syncwarp();

        const float4* vbuf = wbuf + (r & 1) * 256;
        float4 v[VPL];
        #pragma unroll
        for (int i = 0; i < VPL; ++i) v[i] = vbuf[lane + 32 * i];
        __syncwarp();                         // all lanes read before refill

        // refill the buffer we just consumed with row r+2
        if (r + 2 < ROWS_PER_WARP)
            stage_row(wbuf_addr + (r & 1) * 4096, base + (r + 2) * 256 + lane);
        asm volatile("cp.async.commit_group;\n");   // empty group ok

        float p = 0.f;
        #pragma unroll
        for (int i = 0; i < VPL; ++i)
            p += v[i].x * g[i].x + v[i].y * g[i].y + v[i].z * g[i].z + v[i].w * g[i].w;

        #pragma unroll
        for (int off = 16; off; off >>= 1)
            p += __shfl_xor_sync(0xFFFFFFFFu, p, off);   // all lanes get sum

        if (lane == 0) g_scores[(size_t)b * SEQ + row0 + r] = p;

        if (p > m) {                          // warp-uniform, rare
            const float scale = __expf(m - p);
            Z *= scale;
            #pragma unroll
            for (int i = 0; i < VPL; ++i) {
                c[i].x *= scale; c[i].y *= scale;
                c[i].z *= scale; c[i].w *= scale;
            }
            m = p;
        }
        const float e = __expf(p - m);
        Z += e;
        #pragma unroll
        for (int i = 0; i < VPL; ++i) {
            c[i].x += e * v[i].x;  c[i].y += e * v[i].y;
            c[i].z += e * v[i].z;  c[i].w += e * v[i].w;
        }
    }

    // ---- per-CTA combine of the 8 warps (reuse staging smem) ----
    asm volatile("cp.async.wait_group 0;\n");
    __syncthreads();
    float* s_c = (float*)sbuf;                // 8 x 1024 floats = 32 KB
    #pragma unroll
    for (int i = 0; i < VPL; ++i)
        ((float4*)(s_c + warp * HID))[lane + 32 * i] = c[i];
    if (lane == 0) { s_m[warp] = m; s_Z[warp] = Z; }
    __syncthreads();

    float mg = s_m[0];
    #pragma unroll
    for (int w = 1; w < WARPS; ++w) mg = fmaxf(mg, s_m[w]);

    float wsc[WARPS], Zg = 0.f;
    #pragma unroll
    for (int w = 0; w < WARPS; ++w) {
        wsc[w] = __expf(s_m[w] - mg);
        Zg += s_Z[w] * wsc[w];
    }

    float4 acc = make_float4(0.f, 0.f, 0.f, 0.f);
    #pragma unroll
    for (int w = 0; w < WARPS; ++w) {
        float4 cw = ((const float4*)(s_c + w * HID))[t];
        acc.x += wsc[w] * cw.x;  acc.y += wsc[w] * cw.y;
        acc.z += wsc[w] * cw.z;  acc.w += wsc[w] * cw.w;
    }
    ((float4*)(g_cpart + ((size_t)b * NSPLIT + split) * HID))[t] = acc;
    if (t == 0) {
        g_mzpart[(b * NSPLIT + split) * 2 + 0] = mg;
        g_mzpart[(b * NSPLIT + split) * 2 + 1] = Zg;
    }
}

// ---------------------------------------------------------------------------
// Kernel 3/4: cross-split reduction -> c_t, builds cat buffer, AND writes the
// final softmax weights (fused). grid = BATCH, block = 256.
// ---------------------------------------------------------------------------
__global__ void __launch_bounds__(256)
reduce_c_kernel(const float* __restrict__ x, const float* __restrict__ topic,
                float* __restrict__ out_w)
{
    const int b = blockIdx.x;
    const int t = threadIdx.x;

    float mg = -FLT_MAX;
    #pragma unroll
    for (int i = 0; i < NSPLIT; ++i)
        mg = fmaxf(mg, g_mzpart[(b * NSPLIT + i) * 2 + 0]);

    float Zg = 0.f;
    float wsc[NSPLIT];
    #pragma unroll
    for (int i = 0; i < NSPLIT; ++i) {
        float mi = g_mzpart[(b * NSPLIT + i) * 2 + 0];
        float zi = g_mzpart[(b * NSPLIT + i) * 2 + 1];
        wsc[i] = __expf(mi - mg);
        Zg += zi * wsc[i];
    }
    const float inv = 1.f / Zg;

    float4 c = make_float4(0.f, 0.f, 0.f, 0.f);
    #pragma unroll
    for (int i = 0; i < NSPLIT; ++i) {
        float4 cp = ((const float4*)(g_cpart + ((size_t)b * NSPLIT + i) * HID))[t];
        c.x += wsc[i] * cp.x;  c.y += wsc[i] * cp.y;
        c.z += wsc[i] * cp.z;  c.w += wsc[i] * cp.w;
    }
    c.x *= inv; c.y *= inv; c.z *= inv; c.w *= inv;

    ((float4*)(g_cat + (size_t)b * CATK))[t] = c;
    ((float4*)(g_cat + (size_t)b * CATK + HID))[t] =
        ((const float4*)(x + (size_t)b * HID))[t];
    if (t < TOP / 4)
        ((float4*)(g_cat + (size_t)b * CATK + 2 * HID))[t] =
            ((const float4*)(topic + (size_t)b * TOP))[t];

    // fused: weights[b][s] = exp(score - mg) * inv
    const float4* sc = (const float4*)(g_scores + (size_t)b * SEQ);
    float4*       ow = (float4*)(out_w + (size_t)b * SEQ);
    #pragma unroll
    for (int i = 0; i < SEQ / 4 / 256; ++i) {
        float4 s = sc[t + i * 256];
        float4 w;
        w.x = __expf(s.x - mg) * inv;
        w.y = __expf(s.y - mg) * inv;
        w.z = __expf(s.z - mg) * inv;
        w.w = __expf(s.w - mg) * inv;
        ow[t + i * 256] = w;
    }
}

// ---------------------------------------------------------------------------
extern "C" void kernel_launch(void* const* d_in, const int* in_sizes, int n_in,
                              void* d_out, int out_size)
{
    const float* x     = (const float*)d_in[0];
    const float* ctx   = (const float*)d_in[1];
    const float* topic = (const float*)d_in[2];
    const float* W_in  = (const float*)d_in[3];
    const float* b_in  = (const float*)d_in[4];
    const float* W_out = (const float*)d_in[5];
    const float* b_out = (const float*)d_in[6];

    float* out  = (float*)d_out;                 // [BATCH,HID] output
    float* outw = out + BATCH * HID;             // [BATCH,SEQ] weights

    float* gamma_ptr;
    cudaGetSymbolAddress((void**)&gamma_ptr, g_gamma);
    float* cat_ptr;
    cudaGetSymbolAddress((void**)&cat_ptr, g_cat);

    static int smem_set = 0;
    if (!smem_set) {
        cudaFuncSetAttribute(attn_pass_kernel,
                             cudaFuncAttributeMaxDynamicSharedMemorySize,
                             ATTN_SMEM);
        smem_set = 1;
    }

    // 1) gamma = x @ W_in^T + b_in
    small_gemm_kernel<<<HID / 8, 256>>>(x, W_in, b_in, gamma_ptr, HID, HID, 0);

    // 2) fused scores + online softmax + partial c_t (single context pass)
    attn_pass_kernel<<<dim3(NSPLIT, BATCH), 256, ATTN_SMEM>>>(ctx);

    // 3) cross-split reduce + build cat + final weights
    reduce_c_kernel<<<BATCH, 256>>>(x, topic, outw);

    // 4) output = tanh(cat @ W_out^T + b_out)
    small_gemm_kernel<<<HID / 8, 256>>>(cat_ptr, W_out, b_out, out, CATK, HID, 1);
}